// round 10
// baseline (speedup 1.0000x reference)
#include <cuda_runtime.h>
#include <cstdint>

#define B_  8
#define C_  64
#define IC_ 32
#define N_  6400
#define M_  1600
#define GH_ 3200
#define GC_ 6400
#define W_  80
#define WP_ 40

// ---------------- scratch (static device allocations; no runtime alloc) -----
__device__ float g_h[GH_ * M_];          // relu(w1@pos+b1): (3200,1600)
__device__ float g_bias[GC_ * M_];       // geometry bias:   (6400,1600)
__device__ float g_theta[2 * B_ * N_ * IC_]; // (br,b,n,ic)
__device__ float g_phi[2 * B_ * M_ * IC_];   // (br,b,m,ic)
__device__ float g_gv[2 * B_ * M_ * IC_];    // (br,b,m,ic)
__device__ float g_y[2 * B_ * C_ * N_];      // pre-BN W-conv output
__device__ float g_bnsum[2 * C_ * 2];        // per (br,ch): sum, sumsq
__device__ float g_bnsc[2 * C_ * 2];         // per (br,ch): scale, shift

// ---------------- kernel 1: hidden layer of geometry MLP ------------------
__global__ void k_h(const float* __restrict__ pos, const float* __restrict__ w1,
                    const float* __restrict__ b1) {
    int idx = blockIdx.x * 256 + threadIdx.x;
    if (idx >= GH_ * M_) return;
    int m = idx % M_;
    int k = idx / M_;
    float v = fmaf(w1[2 * k], pos[m], fmaf(w1[2 * k + 1], pos[M_ + m], b1[k]));
    g_h[idx] = v > 0.f ? v : 0.f;
}

// ---------------- tf32 m16n8k8 mma helper ---------------------------------
__device__ __forceinline__ void mma_tf32(float* c, const uint32_t* a, const uint32_t* b) {
    asm volatile(
        "mma.sync.aligned.m16n8k8.row.col.f32.tf32.tf32.f32 "
        "{%0,%1,%2,%3}, {%4,%5,%6,%7}, {%8,%9}, {%0,%1,%2,%3};\n"
        : "+f"(c[0]), "+f"(c[1]), "+f"(c[2]), "+f"(c[3])
        : "r"(a[0]), "r"(a[1]), "r"(a[2]), "r"(a[3]), "r"(b[0]), "r"(b[1]));
}

__device__ __forceinline__ void cp16(uint32_t smem_addr, const float* gptr) {
    asm volatile("cp.async.cg.shared.global [%0], [%1], 16;\n" ::"r"(smem_addr),
                 "l"(gptr));
}
__device__ __forceinline__ void cp16z(uint32_t smem_addr, const float* gptr, bool ok) {
    int sz = ok ? 16 : 0;
    asm volatile("cp.async.cg.shared.global [%0], [%1], 16, %2;\n" ::"r"(smem_addr),
                 "l"(gptr), "r"(sz));
}

// ---------------- kernel 2: bias = w2 @ h + b2, tf32 mma + cp.async -------
// 6400x1600, K=3200. 128x128 block tile, now 4 warps (2x2), 64x64 warp tile:
// per ks, 32 LDS feed 32 mma (1.0 LDS/mma vs 1.5 before) -- the GEMM was
// LDS-bound (~199us floor), this cuts the LDS floor to ~133us.
#define GST_ 4
#define AS_ST (128 * 20)
#define BS_ST (16 * 136)
#define GEMM_SMEM_F (GST_ * (AS_ST + BS_ST))
#define GEMM_SMEM_BYTES (GEMM_SMEM_F * 4)

__global__ void __launch_bounds__(128) k_gemm_tc(const float* __restrict__ A,
                                                 const float* __restrict__ b2) {
    extern __shared__ float gsm[];
    const int tid = threadIdx.x;
    const int lane = tid & 31;
    const int wid = tid >> 5;
    const int warp_m = wid >> 1;    // 0..1 (64 rows)
    const int warp_n = wid & 1;     // 0..1 (64 cols)
    const int row0 = blockIdx.y * 128;
    const int col0 = blockIdx.x * 128;

    float acc[4][8][4];
#pragma unroll
    for (int mt = 0; mt < 4; mt++)
#pragma unroll
        for (int nt = 0; nt < 8; nt++)
#pragma unroll
            for (int r = 0; r < 4; r++) acc[mt][nt][r] = 0.f;

    // per-thread copy coords: A row = tid (4 chunks across k), B: 4 chunks
    const bool b_ok[4] = {(col0 + ((tid * 4 + 0) & 31) * 4) < M_,
                          (col0 + ((tid * 4 + 1) & 31) * 4) < M_,
                          (col0 + ((tid * 4 + 2) & 31) * 4) < M_,
                          (col0 + ((tid * 4 + 3) & 31) * 4) < M_};

    auto issue = [&](int st, int k0) {
        float* as = gsm + st * AS_ST;
        float* bs = gsm + GST_ * AS_ST + st * BS_ST;
        uint32_t asa = (uint32_t)__cvta_generic_to_shared(as);
        uint32_t bsa = (uint32_t)__cvta_generic_to_shared(bs);
#pragma unroll
        for (int i = 0; i < 4; i++) {
            // A: row = tid, k-chunk i
            cp16(asa + (tid * 20 + i * 4) * 4,
                 &A[(size_t)(row0 + tid) * GH_ + k0 + i * 4]);
            // B: idx = tid*4+i -> kr, col chunk
            int idx = tid * 4 + i;
            int kr = idx >> 5, c = idx & 31;
            cp16z(bsa + (kr * 136 + c * 4) * 4,
                  &g_h[(size_t)(k0 + kr) * M_ + col0 + c * 4], b_ok[i]);
        }
        asm volatile("cp.async.commit_group;\n");
    };

    const int NKT = GH_ / 16;  // 200
    issue(0, 0);
    issue(1, 16);
    issue(2, 32);

    for (int kt = 0; kt < NKT; kt++) {
        asm volatile("cp.async.wait_group 2;\n");
        __syncthreads();
        if (kt + 3 < NKT) issue((kt + 3) & 3, (kt + 3) * 16);

        const float* as = gsm + (kt & 3) * AS_ST;
        const float* bs = gsm + GST_ * AS_ST + (kt & 3) * BS_ST;
#pragma unroll
        for (int ks = 0; ks < 2; ks++) {
            const int kk = ks * 8;
            uint32_t af[4][4], bf[8][2];
#pragma unroll
            for (int mt = 0; mt < 4; mt++) {
                int r = warp_m * 64 + mt * 16 + (lane >> 2);
                int c = kk + (lane & 3);
                af[mt][0] = __float_as_uint(as[r * 20 + c]);
                af[mt][1] = __float_as_uint(as[(r + 8) * 20 + c]);
                af[mt][2] = __float_as_uint(as[r * 20 + c + 4]);
                af[mt][3] = __float_as_uint(as[(r + 8) * 20 + c + 4]);
            }
#pragma unroll
            for (int nt = 0; nt < 8; nt++) {
                int n = warp_n * 64 + nt * 8 + (lane >> 2);
                int k = kk + (lane & 3);
                bf[nt][0] = __float_as_uint(bs[k * 136 + n]);
                bf[nt][1] = __float_as_uint(bs[(k + 4) * 136 + n]);
            }
#pragma unroll
            for (int mt = 0; mt < 4; mt++)
#pragma unroll
                for (int nt = 0; nt < 8; nt++) mma_tf32(acc[mt][nt], af[mt], bf[nt]);
        }
    }

#pragma unroll
    for (int mt = 0; mt < 4; mt++) {
        int r = row0 + warp_m * 64 + mt * 16 + (lane >> 2);
        float bb0 = b2[r], bb1 = b2[r + 8];
#pragma unroll
        for (int nt = 0; nt < 8; nt++) {
            int c = col0 + warp_n * 64 + nt * 8 + 2 * (lane & 3);
            if (c < M_) {
                *(float2*)&g_bias[(size_t)r * M_ + c] =
                    make_float2(acc[mt][nt][0] + bb0, acc[mt][nt][1] + bb0);
                *(float2*)&g_bias[(size_t)(r + 8) * M_ + c] =
                    make_float2(acc[mt][nt][2] + bb1, acc[mt][nt][3] + bb1);
            }
        }
    }
}

// ---------------- kernel 3: theta conv (both branches), layout (br,b,n,ic) -
__global__ void __launch_bounds__(128) k_theta(const float* __restrict__ rgb,
                                               const float* __restrict__ ir,
                                               const float* __restrict__ wr,
                                               const float* __restrict__ brb,
                                               const float* __restrict__ wi,
                                               const float* __restrict__ bib) {
    __shared__ float wt[C_ * IC_];
    __shared__ float bs[IC_];
    const int br = blockIdx.z, b = blockIdx.y;
    const float* wsrc = br ? wi : wr;
    const float* bsrc = br ? bib : brb;
    for (int i = threadIdx.x; i < C_ * IC_; i += 128) {
        int c = i >> 5, ic = i & 31;
        wt[i] = wsrc[ic * C_ + c];
    }
    if (threadIdx.x < IC_) bs[threadIdx.x] = bsrc[threadIdx.x];
    __syncthreads();
    int n = blockIdx.x * 128 + threadIdx.x;
    const float* x = (br ? ir : rgb) + (size_t)b * C_ * N_ + n;
    float4 acc[8];
#pragma unroll
    for (int i = 0; i < 8; i++) acc[i] = ((const float4*)bs)[i];
#pragma unroll 4
    for (int c = 0; c < C_; c++) {
        float xv = x[(size_t)c * N_];
        const float4* w4 = (const float4*)&wt[c * IC_];
#pragma unroll
        for (int i = 0; i < 8; i++) {
            float4 w = w4[i];
            acc[i].x = fmaf(w.x, xv, acc[i].x);
            acc[i].y = fmaf(w.y, xv, acc[i].y);
            acc[i].z = fmaf(w.z, xv, acc[i].z);
            acc[i].w = fmaf(w.w, xv, acc[i].w);
        }
    }
    float4* dst = (float4*)&g_theta[((size_t)(br * B_ + b) * N_ + n) * IC_];
#pragma unroll
    for (int i = 0; i < 8; i++) dst[i] = acc[i];
}

// ---------------- kernel 4: maxpool + phi + g convs, layout (br,b,m,ic) ----
__global__ void __launch_bounds__(128) k_phig(const float* __restrict__ rgb,
                                              const float* __restrict__ ir,
                                              const float* __restrict__ wpr,
                                              const float* __restrict__ bpr,
                                              const float* __restrict__ wgr,
                                              const float* __restrict__ bgr,
                                              const float* __restrict__ wpi,
                                              const float* __restrict__ bpi,
                                              const float* __restrict__ wgi,
                                              const float* __restrict__ bgi) {
    __shared__ float wp[C_ * IC_], wg[C_ * IC_], bp[IC_], bg[IC_];
    const int br = blockIdx.z, b = blockIdx.y;
    const float* wps = br ? wpi : wpr;
    const float* wgs = br ? wgi : wgr;
    for (int i = threadIdx.x; i < C_ * IC_; i += 128) {
        int c = i >> 5, ic = i & 31;
        wp[i] = wps[ic * C_ + c];
        wg[i] = wgs[ic * C_ + c];
    }
    if (threadIdx.x < IC_) {
        bp[threadIdx.x] = (br ? bpi : bpr)[threadIdx.x];
        bg[threadIdx.x] = (br ? bgi : bgr)[threadIdx.x];
    }
    __syncthreads();
    int m = blockIdx.x * 128 + threadIdx.x;
    if (m >= M_) return;
    int hp = m / WP_, wpos = m % WP_;
    const float* x = (br ? ir : rgb) + (size_t)b * C_ * N_ + (2 * hp) * W_ + 2 * wpos;
    float4 ap[8], ag[8];
#pragma unroll
    for (int i = 0; i < 8; i++) {
        ap[i] = ((const float4*)bp)[i];
        ag[i] = ((const float4*)bg)[i];
    }
#pragma unroll 2
    for (int c = 0; c < C_; c++) {
        const float* p = x + (size_t)c * N_;
        float v = fmaxf(fmaxf(p[0], p[1]), fmaxf(p[W_], p[W_ + 1]));
        const float4* w4p = (const float4*)&wp[c * IC_];
        const float4* w4g = (const float4*)&wg[c * IC_];
#pragma unroll
        for (int i = 0; i < 8; i++) {
            float4 a = w4p[i], g4 = w4g[i];
            ap[i].x = fmaf(a.x, v, ap[i].x);
            ap[i].y = fmaf(a.y, v, ap[i].y);
            ap[i].z = fmaf(a.z, v, ap[i].z);
            ap[i].w = fmaf(a.w, v, ap[i].w);
            ag[i].x = fmaf(g4.x, v, ag[i].x);
            ag[i].y = fmaf(g4.y, v, ag[i].y);
            ag[i].z = fmaf(g4.z, v, ag[i].z);
            ag[i].w = fmaf(g4.w, v, ag[i].w);
        }
    }
    size_t off = ((size_t)(br * B_ + b) * M_ + m) * IC_;
    float4* dp = (float4*)&g_phi[off];
    float4* dg = (float4*)&g_gv[off];
#pragma unroll
    for (int i = 0; i < 8; i++) {
        dp[i] = ap[i];
        dg[i] = ag[i];
    }
}

// ---------------- kernel 5: tensor-core attention + W conv ----------------
// (validated R9 configuration: 128 threads, 4 warps, 32 queries/warp)
#define QB_  128
#define CHK_ 160
#define NT_  (CHK_ / 8)
#define TS_  36
#define GS_  40
#define OS_  34
#define TH_OFF  0
#define PHI_OFF (QB_ * TS_)
#define G_OFF   (PHI_OFF + CHK_ * TS_)
#define WS_OFF  (G_OFF + CHK_ * GS_)
#define WB_OFF  (WS_OFF + C_ * IC_)
#define SMEM_F  (WB_OFF + C_)
#define SMEM_BYTES_ (SMEM_F * 4)

__global__ void __launch_bounds__(128) k_attn_tc(const float* __restrict__ Wwr,
                                                 const float* __restrict__ Wbr,
                                                 const float* __restrict__ Wwi,
                                                 const float* __restrict__ Wbi) {
    extern __shared__ float sm[];
    float* th_s = sm + TH_OFF;
    float* phi_s = sm + PHI_OFF;
    float* gv_s = sm + G_OFF;
    float* Ws = sm + WS_OFF;
    float* Wbs = sm + WB_OFF;

    const int br = blockIdx.z, b = blockIdx.y;
    const int tid = threadIdx.x, lane = tid & 31, w = tid >> 5;
    const int g = lane >> 2, t = lane & 3;
    const int q0 = blockIdx.x * QB_;
    const int qw = w * 32;

    {
        const float* s = br ? Wwi : Wwr;
        for (int i = tid; i < C_ * IC_; i += 128) Ws[i] = s[i];
        if (tid < C_) Wbs[tid] = (br ? Wbi : Wbr)[tid];
        size_t tbase = ((size_t)(br * B_ + b) * N_ + q0) * IC_;
        for (int i = tid; i < QB_ * 8; i += 128) {
            int r = i >> 3, j = i & 7;
            *(float4*)&th_s[r * TS_ + j * 4] = *(const float4*)&g_theta[tbase + r * 32 + j * 4];
        }
    }
    __syncthreads();

    uint32_t athe[2][4][4];
#pragma unroll
    for (int tt = 0; tt < 2; tt++) {
        int r0 = qw + tt * 16 + g;
#pragma unroll
        for (int kk = 0; kk < 4; kk++) {
            int c = kk * 8 + t;
            athe[tt][kk][0] = __float_as_uint(th_s[r0 * TS_ + c]);
            athe[tt][kk][1] = __float_as_uint(th_s[(r0 + 8) * TS_ + c]);
            athe[tt][kk][2] = __float_as_uint(th_s[r0 * TS_ + c + 4]);
            athe[tt][kk][3] = __float_as_uint(th_s[(r0 + 8) * TS_ + c + 4]);
        }
    }

    float acc_o[2][4][4];
#pragma unroll
    for (int tt = 0; tt < 2; tt++)
#pragma unroll
        for (int i = 0; i < 4; i++)
#pragma unroll
            for (int j = 0; j < 4; j++) acc_o[tt][i][j] = 0.f;
    float l0 = 0.f, l1 = 0.f, l2 = 0.f, l3 = 0.f;

    const float* brow = &g_bias[(size_t)(q0 + qw + g) * M_];
    const size_t kvbase = (size_t)(br * B_ + b) * M_ * IC_;
    const int src0 = (lane & ~3) | (t >> 1);
    const int src2 = src0 + 2;
    const bool odd = (t & 1);

    for (int m0 = 0; m0 < M_; m0 += CHK_) {
        __syncthreads();
        for (int i = tid; i < CHK_ * 8; i += 128) {
            int r = i >> 3, j = i & 7;
            *(float4*)&phi_s[r * TS_ + j * 4] =
                *(const float4*)&g_phi[kvbase + (size_t)(m0 + r) * 32 + j * 4];
            *(float4*)&gv_s[r * GS_ + j * 4] =
                *(const float4*)&g_gv[kvbase + (size_t)(m0 + r) * 32 + j * 4];
        }
        __syncthreads();

#pragma unroll 2
        for (int nt = 0; nt < NT_; nt++) {
            float sa[4] = {0.f, 0.f, 0.f, 0.f};
            float sb[4] = {0.f, 0.f, 0.f, 0.f};
#pragma unroll
            for (int kk = 0; kk < 4; kk++) {
                uint32_t bb[2];
                bb[0] = __float_as_uint(phi_s[(nt * 8 + g) * TS_ + kk * 8 + t]);
                bb[1] = __float_as_uint(phi_s[(nt * 8 + g) * TS_ + kk * 8 + t + 4]);
                mma_tf32(sa, athe[0][kk], bb);
                mma_tf32(sb, athe[1][kk], bb);
            }
            int mcol = m0 + nt * 8 + 2 * t;
            float2 bi0 = *(const float2*)&brow[mcol];
            float2 bi1 = *(const float2*)&brow[8 * M_ + mcol];
            float2 bi2 = *(const float2*)&brow[16 * M_ + mcol];
            float2 bi3 = *(const float2*)&brow[24 * M_ + mcol];
            float p0 = __expf(sa[0] + bi0.x);
            float p1 = __expf(sa[1] + bi0.y);
            float p2 = __expf(sa[2] + bi1.x);
            float p3 = __expf(sa[3] + bi1.y);
            float p4 = __expf(sb[0] + bi2.x);
            float p5 = __expf(sb[1] + bi2.y);
            float p6 = __expf(sb[2] + bi3.x);
            float p7 = __expf(sb[3] + bi3.y);
            l0 += p0 + p1;
            l1 += p2 + p3;
            l2 += p4 + p5;
            l3 += p6 + p7;
            uint32_t pa0[4], pa1[4];
            {
                float x00 = __shfl_sync(0xffffffffu, p0, src0);
                float x01 = __shfl_sync(0xffffffffu, p1, src0);
                float x20 = __shfl_sync(0xffffffffu, p0, src2);
                float x21 = __shfl_sync(0xffffffffu, p1, src2);
                float y00 = __shfl_sync(0xffffffffu, p2, src0);
                float y01 = __shfl_sync(0xffffffffu, p3, src0);
                float y20 = __shfl_sync(0xffffffffu, p2, src2);
                float y21 = __shfl_sync(0xffffffffu, p3, src2);
                pa0[0] = __float_as_uint(odd ? x01 : x00);
                pa0[1] = __float_as_uint(odd ? y01 : y00);
                pa0[2] = __float_as_uint(odd ? x21 : x20);
                pa0[3] = __float_as_uint(odd ? y21 : y20);
            }
            {
                float x00 = __shfl_sync(0xffffffffu, p4, src0);
                float x01 = __shfl_sync(0xffffffffu, p5, src0);
                float x20 = __shfl_sync(0xffffffffu, p4, src2);
                float x21 = __shfl_sync(0xffffffffu, p5, src2);
                float y00 = __shfl_sync(0xffffffffu, p6, src0);
                float y01 = __shfl_sync(0xffffffffu, p7, src0);
                float y20 = __shfl_sync(0xffffffffu, p6, src2);
                float y21 = __shfl_sync(0xffffffffu, p7, src2);
                pa1[0] = __float_as_uint(odd ? x01 : x00);
                pa1[1] = __float_as_uint(odd ? y01 : y00);
                pa1[2] = __float_as_uint(odd ? x21 : x20);
                pa1[3] = __float_as_uint(odd ? y21 : y20);
            }
#pragma unroll
            for (int nc = 0; nc < 4; nc++) {
                uint32_t gb[2];
                gb[0] = __float_as_uint(gv_s[(nt * 8 + t) * GS_ + nc * 8 + g]);
                gb[1] = __float_as_uint(gv_s[(nt * 8 + t + 4) * GS_ + nc * 8 + g]);
                mma_tf32(acc_o[0][nc], pa0, gb);
                mma_tf32(acc_o[1][nc], pa1, gb);
            }
        }
    }

    l0 += __shfl_xor_sync(0xffffffffu, l0, 1);
    l0 += __shfl_xor_sync(0xffffffffu, l0, 2);
    l1 += __shfl_xor_sync(0xffffffffu, l1, 1);
    l1 += __shfl_xor_sync(0xffffffffu, l1, 2);
    l2 += __shfl_xor_sync(0xffffffffu, l2, 1);
    l2 += __shfl_xor_sync(0xffffffffu, l2, 2);
    l3 += __shfl_xor_sync(0xffffffffu, l3, 1);
    l3 += __shfl_xor_sync(0xffffffffu, l3, 2);
    float inv0 = 1.f / l0, inv1 = 1.f / l1, inv2 = 1.f / l2, inv3 = 1.f / l3;
#pragma unroll
    for (int nc = 0; nc < 4; nc++) {
        acc_o[0][nc][0] *= inv0;
        acc_o[0][nc][1] *= inv0;
        acc_o[0][nc][2] *= inv1;
        acc_o[0][nc][3] *= inv1;
        acc_o[1][nc][0] *= inv2;
        acc_o[1][nc][1] *= inv2;
        acc_o[1][nc][2] *= inv3;
        acc_o[1][nc][3] *= inv3;
    }

    __syncthreads();
    float* o_s = th_s;
#pragma unroll
    for (int tt = 0; tt < 2; tt++) {
        int r0 = qw + tt * 16 + g;
#pragma unroll
        for (int nc = 0; nc < 4; nc++) {
            *(float2*)&o_s[r0 * OS_ + nc * 8 + 2 * t] =
                make_float2(acc_o[tt][nc][0], acc_o[tt][nc][1]);
            *(float2*)&o_s[(r0 + 8) * OS_ + nc * 8 + 2 * t] =
                make_float2(acc_o[tt][nc][2], acc_o[tt][nc][3]);
        }
    }
    __syncthreads();

    {
        int q = tid;
        float ov[32];
#pragma unroll
        for (int k = 0; k < 16; k++) {
            float2 v = *(const float2*)&o_s[q * OS_ + 2 * k];
            ov[2 * k] = v.x;
            ov[2 * k + 1] = v.y;
        }
        size_t ybase = (size_t)(br * B_ + b) * C_ * N_ + q0 + q;
#pragma unroll 4
        for (int ch = 0; ch < C_; ch++) {
            const float4* wr4 = (const float4*)&Ws[ch * IC_];
            float a0 = Wbs[ch], a1 = 0.f, a2 = 0.f, a3 = 0.f;
#pragma unroll
            for (int k = 0; k < 8; k++) {
                float4 wv = wr4[k];
                a0 = fmaf(wv.x, ov[4 * k + 0], a0);
                a1 = fmaf(wv.y, ov[4 * k + 1], a1);
                a2 = fmaf(wv.z, ov[4 * k + 2], a2);
                a3 = fmaf(wv.w, ov[4 * k + 3], a3);
            }
            g_y[ybase + (size_t)ch * N_] = (a0 + a1) + (a2 + a3);
        }
    }
}

// ---------------- kernel 5b: BN sum/sumsq from g_y ------------------------
__global__ void __launch_bounds__(256) k_bn_reduce() {
    int br = blockIdx.x >> 6;
    int ch = blockIdx.x & 63;
    float s1 = 0.f, s2 = 0.f;
    for (int b = 0; b < B_; b++) {
        const float4* p = (const float4*)&g_y[((size_t)(br * B_ + b) * C_ + ch) * N_];
        for (int i = threadIdx.x; i < N_ / 4; i += 256) {
            float4 v = p[i];
            s1 += (v.x + v.y) + (v.z + v.w);
            s2 = fmaf(v.x, v.x, s2);
            s2 = fmaf(v.y, v.y, s2);
            s2 = fmaf(v.z, v.z, s2);
            s2 = fmaf(v.w, v.w, s2);
        }
    }
    __shared__ float r1[256], r2[256];
    r1[threadIdx.x] = s1;
    r2[threadIdx.x] = s2;
    __syncthreads();
    for (int s = 128; s > 0; s >>= 1) {
        if (threadIdx.x < s) {
            r1[threadIdx.x] += r1[threadIdx.x + s];
            r2[threadIdx.x] += r2[threadIdx.x + s];
        }
        __syncthreads();
    }
    if (threadIdx.x == 0) {
        g_bnsum[(br * C_ + ch) * 2 + 0] = r1[0];
        g_bnsum[(br * C_ + ch) * 2 + 1] = r2[0];
    }
}

// ---------------- kernel 6: BN stats -> per-channel scale/shift ------------
__global__ void k_bnstats(const float* __restrict__ gr, const float* __restrict__ bbr,
                          const float* __restrict__ gi, const float* __restrict__ bbi) {
    int i = threadIdx.x;
    if (i >= 2 * C_) return;
    int br = i / C_, ch = i % C_;
    float cnt = (float)(B_ * N_);
    float s = g_bnsum[i * 2], s2 = g_bnsum[i * 2 + 1];
    float mean = s / cnt;
    float var = s2 / cnt - mean * mean;
    if (var < 0.f) var = 0.f;
    float gamma = (br ? gi : gr)[ch];
    float beta = (br ? bbi : bbr)[ch];
    float sc = gamma * rsqrtf(var + 1e-5f);
    g_bnsc[i * 2 + 0] = sc;
    g_bnsc[i * 2 + 1] = beta - mean * sc;
}

// ---------------- kernel 7: BN apply + residual + write output -------------
__global__ void k_final(const float* __restrict__ rgb, const float* __restrict__ ir,
                        float* __restrict__ out) {
    size_t idx = ((size_t)blockIdx.x * 256 + threadIdx.x) * 4;
    const size_t half = (size_t)B_ * C_ * N_;
    if (idx >= 2 * half) return;
    int br = idx >= half;
    size_t rem = idx - (size_t)br * half;
    int ch = (int)((rem / N_) % C_);
    float4 y = *(const float4*)&g_y[idx];
    float4 xv = *(const float4*)&((br ? ir : rgb)[rem]);
    float sc = g_bnsc[(br * C_ + ch) * 2 + 0];
    float sh = g_bnsc[(br * C_ + ch) * 2 + 1];
    float4 r;
    r.x = fmaf(y.x, sc, sh) + xv.x;
    r.y = fmaf(y.y, sc, sh) + xv.y;
    r.z = fmaf(y.z, sc, sh) + xv.z;
    r.w = fmaf(y.w, sc, sh) + xv.w;
    *(float4*)&out[idx] = r;
}

// ---------------- launcher -------------------------------------------------
extern "C" void kernel_launch(void* const* d_in, const int* in_sizes, int n_in,
                              void* d_out, int out_size) {
    const float* rgb   = (const float*)d_in[0];
    const float* ir    = (const float*)d_in[1];
    const float* pos   = (const float*)d_in[2];
    const float* gp_w1 = (const float*)d_in[3];
    const float* gp_b1 = (const float*)d_in[4];
    const float* gp_w2 = (const float*)d_in[5];
    const float* gp_b2 = (const float*)d_in[6];
    const float* r_tw = (const float*)d_in[7];
    const float* r_tb = (const float*)d_in[8];
    const float* r_pw = (const float*)d_in[9];
    const float* r_pb = (const float*)d_in[10];
    const float* r_gw = (const float*)d_in[11];
    const float* r_gb = (const float*)d_in[12];
    const float* r_Ww = (const float*)d_in[13];
    const float* r_Wb = (const float*)d_in[14];
    const float* r_bg = (const float*)d_in[15];
    const float* r_bb = (const float*)d_in[16];
    const float* i_tw = (const float*)d_in[17];
    const float* i_tb = (const float*)d_in[18];
    const float* i_pw = (const float*)d_in[19];
    const float* i_pb = (const float*)d_in[20];
    const float* i_gw = (const float*)d_in[21];
    const float* i_gb = (const float*)d_in[22];
    const float* i_Ww = (const float*)d_in[23];
    const float* i_Wb = (const float*)d_in[24];
    const float* i_bg = (const float*)d_in[25];
    const float* i_bb = (const float*)d_in[26];
    float* out = (float*)d_out;

    static int smem_set = 0;
    if (!smem_set) {
        cudaFuncSetAttribute(k_attn_tc, cudaFuncAttributeMaxDynamicSharedMemorySize,
                             SMEM_BYTES_);
        cudaFuncSetAttribute(k_gemm_tc, cudaFuncAttributeMaxDynamicSharedMemorySize,
                             GEMM_SMEM_BYTES);
        smem_set = 1;
    }

    k_h<<<(GH_ * M_ + 255) / 256, 256>>>(pos, gp_w1, gp_b1);
    k_gemm_tc<<<dim3((M_ + 127) / 128, GC_ / 128), 128, GEMM_SMEM_BYTES>>>(gp_w2, gp_b2);
    k_theta<<<dim3(N_ / 128, B_, 2), 128>>>(rgb, ir, r_tw, r_tb, i_tw, i_tb);
    k_phig<<<dim3((M_ + 127) / 128, B_, 2), 128>>>(rgb, ir, r_pw, r_pb, r_gw, r_gb,
                                                   i_pw, i_pb, i_gw, i_gb);
    k_attn_tc<<<dim3(N_ / QB_, B_, 2), 128, SMEM_BYTES_>>>(r_Ww, r_Wb, i_Ww, i_Wb);
    k_bn_reduce<<<2 * C_, 256>>>();
    k_bnstats<<<1, 128>>>(r_bg, r_bb, i_bg, i_bb);
    k_final<<<(int)((2ULL * B_ * C_ * N_ / 4 + 255) / 256), 256>>>(rgb, ir, out);
}

// round 11
// speedup vs baseline: 1.1303x; 1.1303x over previous
#include <cuda_runtime.h>
#include <cstdint>

#define B_  8
#define C_  64
#define IC_ 32
#define N_  6400
#define M_  1600
#define GH_ 3200
#define GC_ 6400
#define W_  80
#define WP_ 40

// ---------------- scratch (static device allocations; no runtime alloc) -----
__device__ float g_h[GH_ * M_];          // relu(w1@pos+b1): (3200,1600)
__device__ float g_bias[GC_ * M_];       // geometry bias:   (6400,1600)
__device__ float g_theta[2 * B_ * N_ * IC_]; // (br,b,n,ic)
__device__ float g_phi[2 * B_ * M_ * IC_];   // (br,b,m,ic)
__device__ float g_gv[2 * B_ * M_ * IC_];    // (br,b,m,ic)
__device__ float g_y[2 * B_ * C_ * N_];      // pre-BN W-conv output
__device__ float g_bnsum[2 * C_ * 2];        // per (br,ch): sum, sumsq
__device__ float g_bnsc[2 * C_ * 2];         // per (br,ch): scale, shift

// ---------------- kernel 1: hidden layer of geometry MLP ------------------
__global__ void k_h(const float* __restrict__ pos, const float* __restrict__ w1,
                    const float* __restrict__ b1) {
    int idx = blockIdx.x * 256 + threadIdx.x;
    if (idx >= GH_ * M_) return;
    int m = idx % M_;
    int k = idx / M_;
    float v = fmaf(w1[2 * k], pos[m], fmaf(w1[2 * k + 1], pos[M_ + m], b1[k]));
    g_h[idx] = v > 0.f ? v : 0.f;
}

// ---------------- tf32 m16n8k8 mma helper ---------------------------------
__device__ __forceinline__ void mma_tf32(float* c, const uint32_t* a, const uint32_t* b) {
    asm volatile(
        "mma.sync.aligned.m16n8k8.row.col.f32.tf32.tf32.f32 "
        "{%0,%1,%2,%3}, {%4,%5,%6,%7}, {%8,%9}, {%0,%1,%2,%3};\n"
        : "+f"(c[0]), "+f"(c[1]), "+f"(c[2]), "+f"(c[3])
        : "r"(a[0]), "r"(a[1]), "r"(a[2]), "r"(a[3]), "r"(b[0]), "r"(b[1]));
}

__device__ __forceinline__ void cp16(uint32_t smem_addr, const float* gptr) {
    asm volatile("cp.async.cg.shared.global [%0], [%1], 16;\n" ::"r"(smem_addr),
                 "l"(gptr));
}
__device__ __forceinline__ void cp16z(uint32_t smem_addr, const float* gptr, bool ok) {
    int sz = ok ? 16 : 0;
    asm volatile("cp.async.cg.shared.global [%0], [%1], 16, %2;\n" ::"r"(smem_addr),
                 "l"(gptr), "r"(sz));
}

// ---------------- kernel 2: bias = w2 @ h + b2, tf32 mma + cp.async -------
// (validated R6/R9 configuration: 256 threads, 8 warps, 64x32 warp tile)
#define GST_ 4
#define AS_ST (128 * 20)
#define BS_ST (16 * 136)
#define GEMM_SMEM_F (GST_ * (AS_ST + BS_ST))
#define GEMM_SMEM_BYTES (GEMM_SMEM_F * 4)

__global__ void __launch_bounds__(256) k_gemm_tc(const float* __restrict__ A,
                                                 const float* __restrict__ b2) {
    extern __shared__ float gsm[];
    const int tid = threadIdx.x;
    const int lane = tid & 31;
    const int wid = tid >> 5;
    const int warp_m = wid >> 2;
    const int warp_n = wid & 3;
    const int row0 = blockIdx.y * 128;
    const int col0 = blockIdx.x * 128;

    float acc[4][4][4];
#pragma unroll
    for (int mt = 0; mt < 4; mt++)
#pragma unroll
        for (int nt = 0; nt < 4; nt++)
#pragma unroll
            for (int r = 0; r < 4; r++) acc[mt][nt][r] = 0.f;

    const int a_r0 = (tid * 2) >> 2, a_c0 = (tid * 2) & 3;
    const int a_r1 = (tid * 2 + 1) >> 2, a_c1 = (tid * 2 + 1) & 3;
    const int b_k0 = (tid * 2) >> 5, b_c0 = (tid * 2) & 31;
    const int b_k1 = (tid * 2 + 1) >> 5, b_c1 = (tid * 2 + 1) & 31;

    auto issue = [&](int st, int k0) {
        float* as = gsm + st * AS_ST;
        float* bs = gsm + GST_ * AS_ST + st * BS_ST;
        uint32_t asa = (uint32_t)__cvta_generic_to_shared(as);
        uint32_t bsa = (uint32_t)__cvta_generic_to_shared(bs);
        cp16(asa + (a_r0 * 20 + a_c0 * 4) * 4,
             &A[(size_t)(row0 + a_r0) * GH_ + k0 + a_c0 * 4]);
        cp16(asa + (a_r1 * 20 + a_c1 * 4) * 4,
             &A[(size_t)(row0 + a_r1) * GH_ + k0 + a_c1 * 4]);
        int col0b = col0 + b_c0 * 4, col1b = col0 + b_c1 * 4;
        cp16z(bsa + (b_k0 * 136 + b_c0 * 4) * 4,
              &g_h[(size_t)(k0 + b_k0) * M_ + col0b], col0b < M_);
        cp16z(bsa + (b_k1 * 136 + b_c1 * 4) * 4,
              &g_h[(size_t)(k0 + b_k1) * M_ + col1b], col1b < M_);
        asm volatile("cp.async.commit_group;\n");
    };

    const int NKT = GH_ / 16;  // 200
    issue(0, 0);
    issue(1, 16);
    issue(2, 32);

    for (int kt = 0; kt < NKT; kt++) {
        asm volatile("cp.async.wait_group 2;\n");
        __syncthreads();
        if (kt + 3 < NKT) issue((kt + 3) & 3, (kt + 3) * 16);

        const float* as = gsm + (kt & 3) * AS_ST;
        const float* bs = gsm + GST_ * AS_ST + (kt & 3) * BS_ST;
#pragma unroll
        for (int ks = 0; ks < 2; ks++) {
            const int kk = ks * 8;
            uint32_t af[4][4], bf[4][2];
#pragma unroll
            for (int mt = 0; mt < 4; mt++) {
                int r = warp_m * 64 + mt * 16 + (lane >> 2);
                int c = kk + (lane & 3);
                af[mt][0] = __float_as_uint(as[r * 20 + c]);
                af[mt][1] = __float_as_uint(as[(r + 8) * 20 + c]);
                af[mt][2] = __float_as_uint(as[r * 20 + c + 4]);
                af[mt][3] = __float_as_uint(as[(r + 8) * 20 + c + 4]);
            }
#pragma unroll
            for (int nt = 0; nt < 4; nt++) {
                int n = warp_n * 32 + nt * 8 + (lane >> 2);
                int k = kk + (lane & 3);
                bf[nt][0] = __float_as_uint(bs[k * 136 + n]);
                bf[nt][1] = __float_as_uint(bs[(k + 4) * 136 + n]);
            }
#pragma unroll
            for (int mt = 0; mt < 4; mt++)
#pragma unroll
                for (int nt = 0; nt < 4; nt++) mma_tf32(acc[mt][nt], af[mt], bf[nt]);
        }
    }

#pragma unroll
    for (int mt = 0; mt < 4; mt++) {
        int r = row0 + warp_m * 64 + mt * 16 + (lane >> 2);
        float bb0 = b2[r], bb1 = b2[r + 8];
#pragma unroll
        for (int nt = 0; nt < 4; nt++) {
            int c = col0 + warp_n * 32 + nt * 8 + 2 * (lane & 3);
            if (c < M_) {
                *(float2*)&g_bias[(size_t)r * M_ + c] =
                    make_float2(acc[mt][nt][0] + bb0, acc[mt][nt][1] + bb0);
                *(float2*)&g_bias[(size_t)(r + 8) * M_ + c] =
                    make_float2(acc[mt][nt][2] + bb1, acc[mt][nt][3] + bb1);
            }
        }
    }
}

// ---------------- kernel 3: theta conv (both branches), layout (br,b,n,ic) -
__global__ void __launch_bounds__(128) k_theta(const float* __restrict__ rgb,
                                               const float* __restrict__ ir,
                                               const float* __restrict__ wr,
                                               const float* __restrict__ brb,
                                               const float* __restrict__ wi,
                                               const float* __restrict__ bib) {
    __shared__ float wt[C_ * IC_];
    __shared__ float bs[IC_];
    const int br = blockIdx.z, b = blockIdx.y;
    const float* wsrc = br ? wi : wr;
    const float* bsrc = br ? bib : brb;
    for (int i = threadIdx.x; i < C_ * IC_; i += 128) {
        int c = i >> 5, ic = i & 31;
        wt[i] = wsrc[ic * C_ + c];
    }
    if (threadIdx.x < IC_) bs[threadIdx.x] = bsrc[threadIdx.x];
    __syncthreads();
    int n = blockIdx.x * 128 + threadIdx.x;
    const float* x = (br ? ir : rgb) + (size_t)b * C_ * N_ + n;
    float4 acc[8];
#pragma unroll
    for (int i = 0; i < 8; i++) acc[i] = ((const float4*)bs)[i];
#pragma unroll 4
    for (int c = 0; c < C_; c++) {
        float xv = x[(size_t)c * N_];
        const float4* w4 = (const float4*)&wt[c * IC_];
#pragma unroll
        for (int i = 0; i < 8; i++) {
            float4 w = w4[i];
            acc[i].x = fmaf(w.x, xv, acc[i].x);
            acc[i].y = fmaf(w.y, xv, acc[i].y);
            acc[i].z = fmaf(w.z, xv, acc[i].z);
            acc[i].w = fmaf(w.w, xv, acc[i].w);
        }
    }
    float4* dst = (float4*)&g_theta[((size_t)(br * B_ + b) * N_ + n) * IC_];
#pragma unroll
    for (int i = 0; i < 8; i++) dst[i] = acc[i];
}

// ---------------- kernel 4: maxpool + phi + g convs, layout (br,b,m,ic) ----
__global__ void __launch_bounds__(128) k_phig(const float* __restrict__ rgb,
                                              const float* __restrict__ ir,
                                              const float* __restrict__ wpr,
                                              const float* __restrict__ bpr,
                                              const float* __restrict__ wgr,
                                              const float* __restrict__ bgr,
                                              const float* __restrict__ wpi,
                                              const float* __restrict__ bpi,
                                              const float* __restrict__ wgi,
                                              const float* __restrict__ bgi) {
    __shared__ float wp[C_ * IC_], wg[C_ * IC_], bp[IC_], bg[IC_];
    const int br = blockIdx.z, b = blockIdx.y;
    const float* wps = br ? wpi : wpr;
    const float* wgs = br ? wgi : wgr;
    for (int i = threadIdx.x; i < C_ * IC_; i += 128) {
        int c = i >> 5, ic = i & 31;
        wp[i] = wps[ic * C_ + c];
        wg[i] = wgs[ic * C_ + c];
    }
    if (threadIdx.x < IC_) {
        bp[threadIdx.x] = (br ? bpi : bpr)[threadIdx.x];
        bg[threadIdx.x] = (br ? bgi : bgr)[threadIdx.x];
    }
    __syncthreads();
    int m = blockIdx.x * 128 + threadIdx.x;
    if (m >= M_) return;
    int hp = m / WP_, wpos = m % WP_;
    const float* x = (br ? ir : rgb) + (size_t)b * C_ * N_ + (2 * hp) * W_ + 2 * wpos;
    float4 ap[8], ag[8];
#pragma unroll
    for (int i = 0; i < 8; i++) {
        ap[i] = ((const float4*)bp)[i];
        ag[i] = ((const float4*)bg)[i];
    }
#pragma unroll 2
    for (int c = 0; c < C_; c++) {
        const float* p = x + (size_t)c * N_;
        float v = fmaxf(fmaxf(p[0], p[1]), fmaxf(p[W_], p[W_ + 1]));
        const float4* w4p = (const float4*)&wp[c * IC_];
        const float4* w4g = (const float4*)&wg[c * IC_];
#pragma unroll
        for (int i = 0; i < 8; i++) {
            float4 a = w4p[i], g4 = w4g[i];
            ap[i].x = fmaf(a.x, v, ap[i].x);
            ap[i].y = fmaf(a.y, v, ap[i].y);
            ap[i].z = fmaf(a.z, v, ap[i].z);
            ap[i].w = fmaf(a.w, v, ap[i].w);
            ag[i].x = fmaf(g4.x, v, ag[i].x);
            ag[i].y = fmaf(g4.y, v, ag[i].y);
            ag[i].z = fmaf(g4.z, v, ag[i].z);
            ag[i].w = fmaf(g4.w, v, ag[i].w);
        }
    }
    size_t off = ((size_t)(br * B_ + b) * M_ + m) * IC_;
    float4* dp = (float4*)&g_phi[off];
    float4* dg = (float4*)&g_gv[off];
#pragma unroll
    for (int i = 0; i < 8; i++) {
        dp[i] = ap[i];
        dg[i] = ag[i];
    }
}

// ---------------- kernel 5: tensor-core attention + W conv ----------------
// (validated R9 configuration: 128 threads, 4 warps, 32 queries/warp)
#define QB_  128
#define CHK_ 160
#define NT_  (CHK_ / 8)
#define TS_  36
#define GS_  40
#define OS_  34
#define TH_OFF  0
#define PHI_OFF (QB_ * TS_)
#define G_OFF   (PHI_OFF + CHK_ * TS_)
#define WS_OFF  (G_OFF + CHK_ * GS_)
#define WB_OFF  (WS_OFF + C_ * IC_)
#define SMEM_F  (WB_OFF + C_)
#define SMEM_BYTES_ (SMEM_F * 4)

__global__ void __launch_bounds__(128) k_attn_tc(const float* __restrict__ Wwr,
                                                 const float* __restrict__ Wbr,
                                                 const float* __restrict__ Wwi,
                                                 const float* __restrict__ Wbi) {
    extern __shared__ float sm[];
    float* th_s = sm + TH_OFF;
    float* phi_s = sm + PHI_OFF;
    float* gv_s = sm + G_OFF;
    float* Ws = sm + WS_OFF;
    float* Wbs = sm + WB_OFF;

    const int br = blockIdx.z, b = blockIdx.y;
    const int tid = threadIdx.x, lane = tid & 31, w = tid >> 5;
    const int g = lane >> 2, t = lane & 3;
    const int q0 = blockIdx.x * QB_;
    const int qw = w * 32;

    {
        const float* s = br ? Wwi : Wwr;
        for (int i = tid; i < C_ * IC_; i += 128) Ws[i] = s[i];
        if (tid < C_) Wbs[tid] = (br ? Wbi : Wbr)[tid];
        size_t tbase = ((size_t)(br * B_ + b) * N_ + q0) * IC_;
        for (int i = tid; i < QB_ * 8; i += 128) {
            int r = i >> 3, j = i & 7;
            *(float4*)&th_s[r * TS_ + j * 4] = *(const float4*)&g_theta[tbase + r * 32 + j * 4];
        }
    }
    __syncthreads();

    uint32_t athe[2][4][4];
#pragma unroll
    for (int tt = 0; tt < 2; tt++) {
        int r0 = qw + tt * 16 + g;
#pragma unroll
        for (int kk = 0; kk < 4; kk++) {
            int c = kk * 8 + t;
            athe[tt][kk][0] = __float_as_uint(th_s[r0 * TS_ + c]);
            athe[tt][kk][1] = __float_as_uint(th_s[(r0 + 8) * TS_ + c]);
            athe[tt][kk][2] = __float_as_uint(th_s[r0 * TS_ + c + 4]);
            athe[tt][kk][3] = __float_as_uint(th_s[(r0 + 8) * TS_ + c + 4]);
        }
    }

    float acc_o[2][4][4];
#pragma unroll
    for (int tt = 0; tt < 2; tt++)
#pragma unroll
        for (int i = 0; i < 4; i++)
#pragma unroll
            for (int j = 0; j < 4; j++) acc_o[tt][i][j] = 0.f;
    float l0 = 0.f, l1 = 0.f, l2 = 0.f, l3 = 0.f;

    const float* brow = &g_bias[(size_t)(q0 + qw + g) * M_];
    const size_t kvbase = (size_t)(br * B_ + b) * M_ * IC_;
    const int src0 = (lane & ~3) | (t >> 1);
    const int src2 = src0 + 2;
    const bool odd = (t & 1);

    for (int m0 = 0; m0 < M_; m0 += CHK_) {
        __syncthreads();
        for (int i = tid; i < CHK_ * 8; i += 128) {
            int r = i >> 3, j = i & 7;
            *(float4*)&phi_s[r * TS_ + j * 4] =
                *(const float4*)&g_phi[kvbase + (size_t)(m0 + r) * 32 + j * 4];
            *(float4*)&gv_s[r * GS_ + j * 4] =
                *(const float4*)&g_gv[kvbase + (size_t)(m0 + r) * 32 + j * 4];
        }
        __syncthreads();

#pragma unroll 2
        for (int nt = 0; nt < NT_; nt++) {
            float sa[4] = {0.f, 0.f, 0.f, 0.f};
            float sb[4] = {0.f, 0.f, 0.f, 0.f};
#pragma unroll
            for (int kk = 0; kk < 4; kk++) {
                uint32_t bb[2];
                bb[0] = __float_as_uint(phi_s[(nt * 8 + g) * TS_ + kk * 8 + t]);
                bb[1] = __float_as_uint(phi_s[(nt * 8 + g) * TS_ + kk * 8 + t + 4]);
                mma_tf32(sa, athe[0][kk], bb);
                mma_tf32(sb, athe[1][kk], bb);
            }
            int mcol = m0 + nt * 8 + 2 * t;
            float2 bi0 = *(const float2*)&brow[mcol];
            float2 bi1 = *(const float2*)&brow[8 * M_ + mcol];
            float2 bi2 = *(const float2*)&brow[16 * M_ + mcol];
            float2 bi3 = *(const float2*)&brow[24 * M_ + mcol];
            float p0 = __expf(sa[0] + bi0.x);
            float p1 = __expf(sa[1] + bi0.y);
            float p2 = __expf(sa[2] + bi1.x);
            float p3 = __expf(sa[3] + bi1.y);
            float p4 = __expf(sb[0] + bi2.x);
            float p5 = __expf(sb[1] + bi2.y);
            float p6 = __expf(sb[2] + bi3.x);
            float p7 = __expf(sb[3] + bi3.y);
            l0 += p0 + p1;
            l1 += p2 + p3;
            l2 += p4 + p5;
            l3 += p6 + p7;
            uint32_t pa0[4], pa1[4];
            {
                float x00 = __shfl_sync(0xffffffffu, p0, src0);
                float x01 = __shfl_sync(0xffffffffu, p1, src0);
                float x20 = __shfl_sync(0xffffffffu, p0, src2);
                float x21 = __shfl_sync(0xffffffffu, p1, src2);
                float y00 = __shfl_sync(0xffffffffu, p2, src0);
                float y01 = __shfl_sync(0xffffffffu, p3, src0);
                float y20 = __shfl_sync(0xffffffffu, p2, src2);
                float y21 = __shfl_sync(0xffffffffu, p3, src2);
                pa0[0] = __float_as_uint(odd ? x01 : x00);
                pa0[1] = __float_as_uint(odd ? y01 : y00);
                pa0[2] = __float_as_uint(odd ? x21 : x20);
                pa0[3] = __float_as_uint(odd ? y21 : y20);
            }
            {
                float x00 = __shfl_sync(0xffffffffu, p4, src0);
                float x01 = __shfl_sync(0xffffffffu, p5, src0);
                float x20 = __shfl_sync(0xffffffffu, p4, src2);
                float x21 = __shfl_sync(0xffffffffu, p5, src2);
                float y00 = __shfl_sync(0xffffffffu, p6, src0);
                float y01 = __shfl_sync(0xffffffffu, p7, src0);
                float y20 = __shfl_sync(0xffffffffu, p6, src2);
                float y21 = __shfl_sync(0xffffffffu, p7, src2);
                pa1[0] = __float_as_uint(odd ? x01 : x00);
                pa1[1] = __float_as_uint(odd ? y01 : y00);
                pa1[2] = __float_as_uint(odd ? x21 : x20);
                pa1[3] = __float_as_uint(odd ? y21 : y20);
            }
#pragma unroll
            for (int nc = 0; nc < 4; nc++) {
                uint32_t gb[2];
                gb[0] = __float_as_uint(gv_s[(nt * 8 + t) * GS_ + nc * 8 + g]);
                gb[1] = __float_as_uint(gv_s[(nt * 8 + t + 4) * GS_ + nc * 8 + g]);
                mma_tf32(acc_o[0][nc], pa0, gb);
                mma_tf32(acc_o[1][nc], pa1, gb);
            }
        }
    }

    l0 += __shfl_xor_sync(0xffffffffu, l0, 1);
    l0 += __shfl_xor_sync(0xffffffffu, l0, 2);
    l1 += __shfl_xor_sync(0xffffffffu, l1, 1);
    l1 += __shfl_xor_sync(0xffffffffu, l1, 2);
    l2 += __shfl_xor_sync(0xffffffffu, l2, 1);
    l2 += __shfl_xor_sync(0xffffffffu, l2, 2);
    l3 += __shfl_xor_sync(0xffffffffu, l3, 1);
    l3 += __shfl_xor_sync(0xffffffffu, l3, 2);
    float inv0 = 1.f / l0, inv1 = 1.f / l1, inv2 = 1.f / l2, inv3 = 1.f / l3;
#pragma unroll
    for (int nc = 0; nc < 4; nc++) {
        acc_o[0][nc][0] *= inv0;
        acc_o[0][nc][1] *= inv0;
        acc_o[0][nc][2] *= inv1;
        acc_o[0][nc][3] *= inv1;
        acc_o[1][nc][0] *= inv2;
        acc_o[1][nc][1] *= inv2;
        acc_o[1][nc][2] *= inv3;
        acc_o[1][nc][3] *= inv3;
    }

    __syncthreads();
    float* o_s = th_s;
#pragma unroll
    for (int tt = 0; tt < 2; tt++) {
        int r0 = qw + tt * 16 + g;
#pragma unroll
        for (int nc = 0; nc < 4; nc++) {
            *(float2*)&o_s[r0 * OS_ + nc * 8 + 2 * t] =
                make_float2(acc_o[tt][nc][0], acc_o[tt][nc][1]);
            *(float2*)&o_s[(r0 + 8) * OS_ + nc * 8 + 2 * t] =
                make_float2(acc_o[tt][nc][2], acc_o[tt][nc][3]);
        }
    }
    __syncthreads();

    {
        int q = tid;
        float ov[32];
#pragma unroll
        for (int k = 0; k < 16; k++) {
            float2 v = *(const float2*)&o_s[q * OS_ + 2 * k];
            ov[2 * k] = v.x;
            ov[2 * k + 1] = v.y;
        }
        size_t ybase = (size_t)(br * B_ + b) * C_ * N_ + q0 + q;
#pragma unroll 4
        for (int ch = 0; ch < C_; ch++) {
            const float4* wr4 = (const float4*)&Ws[ch * IC_];
            float a0 = Wbs[ch], a1 = 0.f, a2 = 0.f, a3 = 0.f;
#pragma unroll
            for (int k = 0; k < 8; k++) {
                float4 wv = wr4[k];
                a0 = fmaf(wv.x, ov[4 * k + 0], a0);
                a1 = fmaf(wv.y, ov[4 * k + 1], a1);
                a2 = fmaf(wv.z, ov[4 * k + 2], a2);
                a3 = fmaf(wv.w, ov[4 * k + 3], a3);
            }
            g_y[ybase + (size_t)ch * N_] = (a0 + a1) + (a2 + a3);
        }
    }
}

// ---------------- kernel 5b: BN sum/sumsq from g_y ------------------------
__global__ void __launch_bounds__(256) k_bn_reduce() {
    int br = blockIdx.x >> 6;
    int ch = blockIdx.x & 63;
    float s1 = 0.f, s2 = 0.f;
    for (int b = 0; b < B_; b++) {
        const float4* p = (const float4*)&g_y[((size_t)(br * B_ + b) * C_ + ch) * N_];
        for (int i = threadIdx.x; i < N_ / 4; i += 256) {
            float4 v = p[i];
            s1 += (v.x + v.y) + (v.z + v.w);
            s2 = fmaf(v.x, v.x, s2);
            s2 = fmaf(v.y, v.y, s2);
            s2 = fmaf(v.z, v.z, s2);
            s2 = fmaf(v.w, v.w, s2);
        }
    }
    __shared__ float r1[256], r2[256];
    r1[threadIdx.x] = s1;
    r2[threadIdx.x] = s2;
    __syncthreads();
    for (int s = 128; s > 0; s >>= 1) {
        if (threadIdx.x < s) {
            r1[threadIdx.x] += r1[threadIdx.x + s];
            r2[threadIdx.x] += r2[threadIdx.x + s];
        }
        __syncthreads();
    }
    if (threadIdx.x == 0) {
        g_bnsum[(br * C_ + ch) * 2 + 0] = r1[0];
        g_bnsum[(br * C_ + ch) * 2 + 1] = r2[0];
    }
}

// ---------------- kernel 6: BN stats -> per-channel scale/shift ------------
__global__ void k_bnstats(const float* __restrict__ gr, const float* __restrict__ bbr,
                          const float* __restrict__ gi, const float* __restrict__ bbi) {
    int i = threadIdx.x;
    if (i >= 2 * C_) return;
    int br = i / C_, ch = i % C_;
    float cnt = (float)(B_ * N_);
    float s = g_bnsum[i * 2], s2 = g_bnsum[i * 2 + 1];
    float mean = s / cnt;
    float var = s2 / cnt - mean * mean;
    if (var < 0.f) var = 0.f;
    float gamma = (br ? gi : gr)[ch];
    float beta = (br ? bbi : bbr)[ch];
    float sc = gamma * rsqrtf(var + 1e-5f);
    g_bnsc[i * 2 + 0] = sc;
    g_bnsc[i * 2 + 1] = beta - mean * sc;
}

// ---------------- kernel 7: BN apply + residual + write output -------------
__global__ void k_final(const float* __restrict__ rgb, const float* __restrict__ ir,
                        float* __restrict__ out) {
    size_t idx = ((size_t)blockIdx.x * 256 + threadIdx.x) * 4;
    const size_t half = (size_t)B_ * C_ * N_;
    if (idx >= 2 * half) return;
    int br = idx >= half;
    size_t rem = idx - (size_t)br * half;
    int ch = (int)((rem / N_) % C_);
    float4 y = *(const float4*)&g_y[idx];
    float4 xv = *(const float4*)&((br ? ir : rgb)[rem]);
    float sc = g_bnsc[(br * C_ + ch) * 2 + 0];
    float sh = g_bnsc[(br * C_ + ch) * 2 + 1];
    float4 r;
    r.x = fmaf(y.x, sc, sh) + xv.x;
    r.y = fmaf(y.y, sc, sh) + xv.y;
    r.z = fmaf(y.z, sc, sh) + xv.z;
    r.w = fmaf(y.w, sc, sh) + xv.w;
    *(float4*)&out[idx] = r;
}

// ---------------- launcher -------------------------------------------------
extern "C" void kernel_launch(void* const* d_in, const int* in_sizes, int n_in,
                              void* d_out, int out_size) {
    const float* rgb   = (const float*)d_in[0];
    const float* ir    = (const float*)d_in[1];
    const float* pos   = (const float*)d_in[2];
    const float* gp_w1 = (const float*)d_in[3];
    const float* gp_b1 = (const float*)d_in[4];
    const float* gp_w2 = (const float*)d_in[5];
    const float* gp_b2 = (const float*)d_in[6];
    const float* r_tw = (const float*)d_in[7];
    const float* r_tb = (const float*)d_in[8];
    const float* r_pw = (const float*)d_in[9];
    const float* r_pb = (const float*)d_in[10];
    const float* r_gw = (const float*)d_in[11];
    const float* r_gb = (const float*)d_in[12];
    const float* r_Ww = (const float*)d_in[13];
    const float* r_Wb = (const float*)d_in[14];
    const float* r_bg = (const float*)d_in[15];
    const float* r_bb = (const float*)d_in[16];
    const float* i_tw = (const float*)d_in[17];
    const float* i_tb = (const float*)d_in[18];
    const float* i_pw = (const float*)d_in[19];
    const float* i_pb = (const float*)d_in[20];
    const float* i_gw = (const float*)d_in[21];
    const float* i_gb = (const float*)d_in[22];
    const float* i_Ww = (const float*)d_in[23];
    const float* i_Wb = (const float*)d_in[24];
    const float* i_bg = (const float*)d_in[25];
    const float* i_bb = (const float*)d_in[26];
    float* out = (float*)d_out;

    static int init_done = 0;
    static cudaStream_t s2;
    static cudaEvent_t ev_fork, ev_join;
    if (!init_done) {
        cudaFuncSetAttribute(k_attn_tc, cudaFuncAttributeMaxDynamicSharedMemorySize,
                             SMEM_BYTES_);
        cudaFuncSetAttribute(k_gemm_tc, cudaFuncAttributeMaxDynamicSharedMemorySize,
                             GEMM_SMEM_BYTES);
        cudaStreamCreateWithFlags(&s2, cudaStreamNonBlocking);
        cudaEventCreateWithFlags(&ev_fork, cudaEventDisableTiming);
        cudaEventCreateWithFlags(&ev_join, cudaEventDisableTiming);
        init_done = 1;
    }

    // fork: theta+phig (side stream) run concurrently with h+gemm (main stream)
    cudaEventRecord(ev_fork, 0);
    cudaStreamWaitEvent(s2, ev_fork, 0);
    k_theta<<<dim3(N_ / 128, B_, 2), 128, 0, s2>>>(rgb, ir, r_tw, r_tb, i_tw, i_tb);
    k_phig<<<dim3((M_ + 127) / 128, B_, 2), 128, 0, s2>>>(
        rgb, ir, r_pw, r_pb, r_gw, r_gb, i_pw, i_pb, i_gw, i_gb);
    cudaEventRecord(ev_join, s2);

    k_h<<<(GH_ * M_ + 255) / 256, 256>>>(pos, gp_w1, gp_b1);
    k_gemm_tc<<<dim3((M_ + 127) / 128, GC_ / 128), 256, GEMM_SMEM_BYTES>>>(gp_w2, gp_b2);

    // join: attention needs bias + theta + phi/g
    cudaStreamWaitEvent(0, ev_join, 0);
    k_attn_tc<<<dim3(N_ / QB_, B_, 2), 128, SMEM_BYTES_>>>(r_Ww, r_Wb, i_Ww, i_Wb);
    k_bn_reduce<<<2 * C_, 256>>>();
    k_bnstats<<<1, 128>>>(r_bg, r_bb, i_bg, i_bb);
    k_final<<<(int)((2ULL * B_ * C_ * N_ / 4 + 255) / 256), 256>>>(rgb, ir, out);
}

// round 12
// speedup vs baseline: 1.5091x; 1.3351x over previous
#include <cuda_runtime.h>
#include <cuda_bf16.h>
#include <cstdint>

#define B_  8
#define C_  64
#define IC_ 32
#define N_  6400
#define M_  1600
#define GH_ 3200
#define GC_ 6400
#define W_  80
#define WP_ 40

// ---------------- scratch (static device allocations; no runtime alloc) -----
__device__ __nv_bfloat16 g_ht[(size_t)M_ * GH_];   // h^T bf16: [m][k]
__device__ __nv_bfloat16 g_w2b[(size_t)GC_ * GH_]; // w2 bf16:  [n][k]
__device__ float g_bias[GC_ * M_];       // geometry bias:   (6400,1600)
__device__ float g_theta[2 * B_ * N_ * IC_]; // (br,b,n,ic)
__device__ float g_phi[2 * B_ * M_ * IC_];   // (br,b,m,ic)
__device__ float g_gv[2 * B_ * M_ * IC_];    // (br,b,m,ic)
__device__ float g_y[2 * B_ * C_ * N_];      // pre-BN W-conv output
__device__ float g_bnsum[2 * C_ * 2];        // per (br,ch): sum, sumsq
__device__ float g_bnsc[2 * C_ * 2];         // per (br,ch): scale, shift

// ---------------- kernel 1a: hidden layer -> transposed bf16 --------------
__global__ void k_ht(const float* __restrict__ pos, const float* __restrict__ w1,
                     const float* __restrict__ b1) {
    int idx = blockIdx.x * 256 + threadIdx.x;
    if (idx >= GH_ * M_) return;
    int k = idx % GH_;
    int m = idx / GH_;
    float v = fmaf(w1[2 * k], pos[m], fmaf(w1[2 * k + 1], pos[M_ + m], b1[k]));
    g_ht[(size_t)m * GH_ + k] = __float2bfloat16(v > 0.f ? v : 0.f);
}

// ---------------- kernel 1b: w2 fp32 -> bf16 ------------------------------
__global__ void k_w2cvt(const float* __restrict__ w2) {
    size_t i = ((size_t)blockIdx.x * 256 + threadIdx.x) * 4;
    if (i >= (size_t)GC_ * GH_) return;
    float4 v = *(const float4*)&w2[i];
    __nv_bfloat162 lo = __floats2bfloat162_rn(v.x, v.y);
    __nv_bfloat162 hi = __floats2bfloat162_rn(v.z, v.w);
    *(__nv_bfloat162*)&g_w2b[i] = lo;
    *(__nv_bfloat162*)&g_w2b[i + 2] = hi;
}

// ---------------- mma helpers ---------------------------------------------
__device__ __forceinline__ void mma_tf32(float* c, const uint32_t* a, const uint32_t* b) {
    asm volatile(
        "mma.sync.aligned.m16n8k8.row.col.f32.tf32.tf32.f32 "
        "{%0,%1,%2,%3}, {%4,%5,%6,%7}, {%8,%9}, {%0,%1,%2,%3};\n"
        : "+f"(c[0]), "+f"(c[1]), "+f"(c[2]), "+f"(c[3])
        : "r"(a[0]), "r"(a[1]), "r"(a[2]), "r"(a[3]), "r"(b[0]), "r"(b[1]));
}
__device__ __forceinline__ void mma_bf16(float* c, const uint32_t* a, const uint32_t* b) {
    asm volatile(
        "mma.sync.aligned.m16n8k16.row.col.f32.bf16.bf16.f32 "
        "{%0,%1,%2,%3}, {%4,%5,%6,%7}, {%8,%9}, {%0,%1,%2,%3};\n"
        : "+f"(c[0]), "+f"(c[1]), "+f"(c[2]), "+f"(c[3])
        : "r"(a[0]), "r"(a[1]), "r"(a[2]), "r"(a[3]), "r"(b[0]), "r"(b[1]));
}

__device__ __forceinline__ void cp16(uint32_t smem_addr, const void* gptr) {
    asm volatile("cp.async.cg.shared.global [%0], [%1], 16;\n" ::"r"(smem_addr),
                 "l"(gptr));
}
__device__ __forceinline__ void cp16z(uint32_t smem_addr, const void* gptr, bool ok) {
    int sz = ok ? 16 : 0;
    asm volatile("cp.async.cg.shared.global [%0], [%1], 16, %2;\n" ::"r"(smem_addr),
                 "l"(gptr), "r"(sz));
}

// ---------------- kernel 2: bias = w2 @ h + b2, bf16 mma + cp.async -------
// 6400x1600, K=3200 bf16. 128x128 tile, 8 warps (2x4), 64x32 warp tile,
// m16n8k16: K-chunk 32 (100 iters), mma count & LDS halved vs tf32.
// Both A and B stored [row][k] bf16, 40 bf16 (20 u32) stride: frag LDS
// pattern (g*20+t) mod 32 hits 32 distinct banks.
#define GST_ 4
#define KC_  32
#define AS_ST (128 * 20)   // u32 units per stage
#define BS_ST (128 * 20)
#define GEMM_SMEM_F (GST_ * (AS_ST + BS_ST))
#define GEMM_SMEM_BYTES (GEMM_SMEM_F * 4)

__global__ void __launch_bounds__(256) k_gemm_tc(const float* __restrict__ b2) {
    extern __shared__ float gsmf[];
    uint32_t* gsm = (uint32_t*)gsmf;
    const int tid = threadIdx.x;
    const int lane = tid & 31;
    const int wid = tid >> 5;
    const int warp_m = wid >> 2;
    const int warp_n = wid & 3;
    const int g = lane >> 2, t = lane & 3;
    const int row0 = blockIdx.y * 128;
    const int col0 = blockIdx.x * 128;

    float acc[4][4][4];
#pragma unroll
    for (int mt = 0; mt < 4; mt++)
#pragma unroll
        for (int nt = 0; nt < 4; nt++)
#pragma unroll
            for (int r = 0; r < 4; r++) acc[mt][nt][r] = 0.f;

    // copy coords: 512 16B chunks per operand per stage, 2 per thread
    const int c_r0 = (tid * 2) >> 2, c_c0 = (tid * 2) & 3;
    const int c_r1 = (tid * 2 + 1) >> 2, c_c1 = (tid * 2 + 1) & 3;
    const bool b_ok0 = (col0 + c_r0) < M_;
    const bool b_ok1 = (col0 + c_r1) < M_;

    auto issue = [&](int st, int k0) {
        uint32_t asa = (uint32_t)__cvta_generic_to_shared(gsm + st * AS_ST);
        uint32_t bsa = (uint32_t)__cvta_generic_to_shared(gsm + GST_ * AS_ST + st * BS_ST);
        cp16(asa + (c_r0 * 20 + c_c0 * 4) * 4,
             &g_w2b[(size_t)(row0 + c_r0) * GH_ + k0 + c_c0 * 8]);
        cp16(asa + (c_r1 * 20 + c_c1 * 4) * 4,
             &g_w2b[(size_t)(row0 + c_r1) * GH_ + k0 + c_c1 * 8]);
        cp16z(bsa + (c_r0 * 20 + c_c0 * 4) * 4,
              &g_ht[(size_t)(col0 + c_r0) * GH_ + k0 + c_c0 * 8], b_ok0);
        cp16z(bsa + (c_r1 * 20 + c_c1 * 4) * 4,
              &g_ht[(size_t)(col0 + c_r1) * GH_ + k0 + c_c1 * 8], b_ok1);
        asm volatile("cp.async.commit_group;\n");
    };

    const int NKT = GH_ / KC_;  // 100
    issue(0, 0);
    issue(1, KC_);
    issue(2, 2 * KC_);

    for (int kt = 0; kt < NKT; kt++) {
        asm volatile("cp.async.wait_group 2;\n");
        __syncthreads();
        if (kt + 3 < NKT) issue((kt + 3) & 3, (kt + 3) * KC_);

        const uint32_t* as = gsm + (kt & 3) * AS_ST;
        const uint32_t* bs = gsm + GST_ * AS_ST + (kt & 3) * BS_ST;
#pragma unroll
        for (int ks = 0; ks < 2; ks++) {
            const int base = ks * 8;
            uint32_t af[4][4], bf[4][2];
#pragma unroll
            for (int mt = 0; mt < 4; mt++) {
                int r = warp_m * 64 + mt * 16 + g;
                af[mt][0] = as[r * 20 + base + t];
                af[mt][1] = as[(r + 8) * 20 + base + t];
                af[mt][2] = as[r * 20 + base + t + 4];
                af[mt][3] = as[(r + 8) * 20 + base + t + 4];
            }
#pragma unroll
            for (int nt = 0; nt < 4; nt++) {
                int n = warp_n * 32 + nt * 8 + g;
                bf[nt][0] = bs[n * 20 + base + t];
                bf[nt][1] = bs[n * 20 + base + t + 4];
            }
#pragma unroll
            for (int mt = 0; mt < 4; mt++)
#pragma unroll
                for (int nt = 0; nt < 4; nt++) mma_bf16(acc[mt][nt], af[mt], bf[nt]);
        }
    }

#pragma unroll
    for (int mt = 0; mt < 4; mt++) {
        int r = row0 + warp_m * 64 + mt * 16 + g;
        float bb0 = b2[r], bb1 = b2[r + 8];
#pragma unroll
        for (int nt = 0; nt < 4; nt++) {
            int c = col0 + warp_n * 32 + nt * 8 + 2 * t;
            if (c < M_) {
                *(float2*)&g_bias[(size_t)r * M_ + c] =
                    make_float2(acc[mt][nt][0] + bb0, acc[mt][nt][1] + bb0);
                *(float2*)&g_bias[(size_t)(r + 8) * M_ + c] =
                    make_float2(acc[mt][nt][2] + bb1, acc[mt][nt][3] + bb1);
            }
        }
    }
}

// ---------------- kernel 3: theta conv (both branches), layout (br,b,n,ic) -
__global__ void __launch_bounds__(128) k_theta(const float* __restrict__ rgb,
                                               const float* __restrict__ ir,
                                               const float* __restrict__ wr,
                                               const float* __restrict__ brb,
                                               const float* __restrict__ wi,
                                               const float* __restrict__ bib) {
    __shared__ float wt[C_ * IC_];
    __shared__ float bs[IC_];
    const int br = blockIdx.z, b = blockIdx.y;
    const float* wsrc = br ? wi : wr;
    const float* bsrc = br ? bib : brb;
    for (int i = threadIdx.x; i < C_ * IC_; i += 128) {
        int c = i >> 5, ic = i & 31;
        wt[i] = wsrc[ic * C_ + c];
    }
    if (threadIdx.x < IC_) bs[threadIdx.x] = bsrc[threadIdx.x];
    __syncthreads();
    int n = blockIdx.x * 128 + threadIdx.x;
    const float* x = (br ? ir : rgb) + (size_t)b * C_ * N_ + n;
    float4 acc[8];
#pragma unroll
    for (int i = 0; i < 8; i++) acc[i] = ((const float4*)bs)[i];
#pragma unroll 4
    for (int c = 0; c < C_; c++) {
        float xv = x[(size_t)c * N_];
        const float4* w4 = (const float4*)&wt[c * IC_];
#pragma unroll
        for (int i = 0; i < 8; i++) {
            float4 w = w4[i];
            acc[i].x = fmaf(w.x, xv, acc[i].x);
            acc[i].y = fmaf(w.y, xv, acc[i].y);
            acc[i].z = fmaf(w.z, xv, acc[i].z);
            acc[i].w = fmaf(w.w, xv, acc[i].w);
        }
    }
    float4* dst = (float4*)&g_theta[((size_t)(br * B_ + b) * N_ + n) * IC_];
#pragma unroll
    for (int i = 0; i < 8; i++) dst[i] = acc[i];
}

// ---------------- kernel 4: maxpool + phi + g convs, layout (br,b,m,ic) ----
__global__ void __launch_bounds__(128) k_phig(const float* __restrict__ rgb,
                                              const float* __restrict__ ir,
                                              const float* __restrict__ wpr,
                                              const float* __restrict__ bpr,
                                              const float* __restrict__ wgr,
                                              const float* __restrict__ bgr,
                                              const float* __restrict__ wpi,
                                              const float* __restrict__ bpi,
                                              const float* __restrict__ wgi,
                                              const float* __restrict__ bgi) {
    __shared__ float wp[C_ * IC_], wg[C_ * IC_], bp[IC_], bg[IC_];
    const int br = blockIdx.z, b = blockIdx.y;
    const float* wps = br ? wpi : wpr;
    const float* wgs = br ? wgi : wgr;
    for (int i = threadIdx.x; i < C_ * IC_; i += 128) {
        int c = i >> 5, ic = i & 31;
        wp[i] = wps[ic * C_ + c];
        wg[i] = wgs[ic * C_ + c];
    }
    if (threadIdx.x < IC_) {
        bp[threadIdx.x] = (br ? bpi : bpr)[threadIdx.x];
        bg[threadIdx.x] = (br ? bgi : bgr)[threadIdx.x];
    }
    __syncthreads();
    int m = blockIdx.x * 128 + threadIdx.x;
    if (m >= M_) return;
    int hp = m / WP_, wpos = m % WP_;
    const float* x = (br ? ir : rgb) + (size_t)b * C_ * N_ + (2 * hp) * W_ + 2 * wpos;
    float4 ap[8], ag[8];
#pragma unroll
    for (int i = 0; i < 8; i++) {
        ap[i] = ((const float4*)bp)[i];
        ag[i] = ((const float4*)bg)[i];
    }
#pragma unroll 2
    for (int c = 0; c < C_; c++) {
        const float* p = x + (size_t)c * N_;
        float v = fmaxf(fmaxf(p[0], p[1]), fmaxf(p[W_], p[W_ + 1]));
        const float4* w4p = (const float4*)&wp[c * IC_];
        const float4* w4g = (const float4*)&wg[c * IC_];
#pragma unroll
        for (int i = 0; i < 8; i++) {
            float4 a = w4p[i], g4 = w4g[i];
            ap[i].x = fmaf(a.x, v, ap[i].x);
            ap[i].y = fmaf(a.y, v, ap[i].y);
            ap[i].z = fmaf(a.z, v, ap[i].z);
            ap[i].w = fmaf(a.w, v, ap[i].w);
            ag[i].x = fmaf(g4.x, v, ag[i].x);
            ag[i].y = fmaf(g4.y, v, ag[i].y);
            ag[i].z = fmaf(g4.z, v, ag[i].z);
            ag[i].w = fmaf(g4.w, v, ag[i].w);
        }
    }
    size_t off = ((size_t)(br * B_ + b) * M_ + m) * IC_;
    float4* dp = (float4*)&g_phi[off];
    float4* dg = (float4*)&g_gv[off];
#pragma unroll
    for (int i = 0; i < 8; i++) {
        dp[i] = ap[i];
        dg[i] = ag[i];
    }
}

// ---------------- kernel 5: tensor-core attention + W conv ----------------
// (validated R9 configuration: 128 threads, 4 warps, 32 queries/warp)
#define QB_  128
#define CHK_ 160
#define NT_  (CHK_ / 8)
#define TS_  36
#define GS_  40
#define OS_  34
#define TH_OFF  0
#define PHI_OFF (QB_ * TS_)
#define G_OFF   (PHI_OFF + CHK_ * TS_)
#define WS_OFF  (G_OFF + CHK_ * GS_)
#define WB_OFF  (WS_OFF + C_ * IC_)
#define SMEM_F  (WB_OFF + C_)
#define SMEM_BYTES_ (SMEM_F * 4)

__global__ void __launch_bounds__(128) k_attn_tc(const float* __restrict__ Wwr,
                                                 const float* __restrict__ Wbr,
                                                 const float* __restrict__ Wwi,
                                                 const float* __restrict__ Wbi) {
    extern __shared__ float sm[];
    float* th_s = sm + TH_OFF;
    float* phi_s = sm + PHI_OFF;
    float* gv_s = sm + G_OFF;
    float* Ws = sm + WS_OFF;
    float* Wbs = sm + WB_OFF;

    const int br = blockIdx.z, b = blockIdx.y;
    const int tid = threadIdx.x, lane = tid & 31, w = tid >> 5;
    const int g = lane >> 2, t = lane & 3;
    const int q0 = blockIdx.x * QB_;
    const int qw = w * 32;

    {
        const float* s = br ? Wwi : Wwr;
        for (int i = tid; i < C_ * IC_; i += 128) Ws[i] = s[i];
        if (tid < C_) Wbs[tid] = (br ? Wbi : Wbr)[tid];
        size_t tbase = ((size_t)(br * B_ + b) * N_ + q0) * IC_;
        for (int i = tid; i < QB_ * 8; i += 128) {
            int r = i >> 3, j = i & 7;
            *(float4*)&th_s[r * TS_ + j * 4] = *(const float4*)&g_theta[tbase + r * 32 + j * 4];
        }
    }
    __syncthreads();

    uint32_t athe[2][4][4];
#pragma unroll
    for (int tt = 0; tt < 2; tt++) {
        int r0 = qw + tt * 16 + g;
#pragma unroll
        for (int kk = 0; kk < 4; kk++) {
            int c = kk * 8 + t;
            athe[tt][kk][0] = __float_as_uint(th_s[r0 * TS_ + c]);
            athe[tt][kk][1] = __float_as_uint(th_s[(r0 + 8) * TS_ + c]);
            athe[tt][kk][2] = __float_as_uint(th_s[r0 * TS_ + c + 4]);
            athe[tt][kk][3] = __float_as_uint(th_s[(r0 + 8) * TS_ + c + 4]);
        }
    }

    float acc_o[2][4][4];
#pragma unroll
    for (int tt = 0; tt < 2; tt++)
#pragma unroll
        for (int i = 0; i < 4; i++)
#pragma unroll
            for (int j = 0; j < 4; j++) acc_o[tt][i][j] = 0.f;
    float l0 = 0.f, l1 = 0.f, l2 = 0.f, l3 = 0.f;

    const float* brow = &g_bias[(size_t)(q0 + qw + g) * M_];
    const size_t kvbase = (size_t)(br * B_ + b) * M_ * IC_;
    const int src0 = (lane & ~3) | (t >> 1);
    const int src2 = src0 + 2;
    const bool odd = (t & 1);

    for (int m0 = 0; m0 < M_; m0 += CHK_) {
        __syncthreads();
        for (int i = tid; i < CHK_ * 8; i += 128) {
            int r = i >> 3, j = i & 7;
            *(float4*)&phi_s[r * TS_ + j * 4] =
                *(const float4*)&g_phi[kvbase + (size_t)(m0 + r) * 32 + j * 4];
            *(float4*)&gv_s[r * GS_ + j * 4] =
                *(const float4*)&g_gv[kvbase + (size_t)(m0 + r) * 32 + j * 4];
        }
        __syncthreads();

#pragma unroll 2
        for (int nt = 0; nt < NT_; nt++) {
            float sa[4] = {0.f, 0.f, 0.f, 0.f};
            float sb[4] = {0.f, 0.f, 0.f, 0.f};
#pragma unroll
            for (int kk = 0; kk < 4; kk++) {
                uint32_t bb[2];
                bb[0] = __float_as_uint(phi_s[(nt * 8 + g) * TS_ + kk * 8 + t]);
                bb[1] = __float_as_uint(phi_s[(nt * 8 + g) * TS_ + kk * 8 + t + 4]);
                mma_tf32(sa, athe[0][kk], bb);
                mma_tf32(sb, athe[1][kk], bb);
            }
            int mcol = m0 + nt * 8 + 2 * t;
            float2 bi0 = *(const float2*)&brow[mcol];
            float2 bi1 = *(const float2*)&brow[8 * M_ + mcol];
            float2 bi2 = *(const float2*)&brow[16 * M_ + mcol];
            float2 bi3 = *(const float2*)&brow[24 * M_ + mcol];
            float p0 = __expf(sa[0] + bi0.x);
            float p1 = __expf(sa[1] + bi0.y);
            float p2 = __expf(sa[2] + bi1.x);
            float p3 = __expf(sa[3] + bi1.y);
            float p4 = __expf(sb[0] + bi2.x);
            float p5 = __expf(sb[1] + bi2.y);
            float p6 = __expf(sb[2] + bi3.x);
            float p7 = __expf(sb[3] + bi3.y);
            l0 += p0 + p1;
            l1 += p2 + p3;
            l2 += p4 + p5;
            l3 += p6 + p7;
            uint32_t pa0[4], pa1[4];
            {
                float x00 = __shfl_sync(0xffffffffu, p0, src0);
                float x01 = __shfl_sync(0xffffffffu, p1, src0);
                float x20 = __shfl_sync(0xffffffffu, p0, src2);
                float x21 = __shfl_sync(0xffffffffu, p1, src2);
                float y00 = __shfl_sync(0xffffffffu, p2, src0);
                float y01 = __shfl_sync(0xffffffffu, p3, src0);
                float y20 = __shfl_sync(0xffffffffu, p2, src2);
                float y21 = __shfl_sync(0xffffffffu, p3, src2);
                pa0[0] = __float_as_uint(odd ? x01 : x00);
                pa0[1] = __float_as_uint(odd ? y01 : y00);
                pa0[2] = __float_as_uint(odd ? x21 : x20);
                pa0[3] = __float_as_uint(odd ? y21 : y20);
            }
            {
                float x00 = __shfl_sync(0xffffffffu, p4, src0);
                float x01 = __shfl_sync(0xffffffffu, p5, src0);
                float x20 = __shfl_sync(0xffffffffu, p4, src2);
                float x21 = __shfl_sync(0xffffffffu, p5, src2);
                float y00 = __shfl_sync(0xffffffffu, p6, src0);
                float y01 = __shfl_sync(0xffffffffu, p7, src0);
                float y20 = __shfl_sync(0xffffffffu, p6, src2);
                float y21 = __shfl_sync(0xffffffffu, p7, src2);
                pa1[0] = __float_as_uint(odd ? x01 : x00);
                pa1[1] = __float_as_uint(odd ? y01 : y00);
                pa1[2] = __float_as_uint(odd ? x21 : x20);
                pa1[3] = __float_as_uint(odd ? y21 : y20);
            }
#pragma unroll
            for (int nc = 0; nc < 4; nc++) {
                uint32_t gb[2];
                gb[0] = __float_as_uint(gv_s[(nt * 8 + t) * GS_ + nc * 8 + g]);
                gb[1] = __float_as_uint(gv_s[(nt * 8 + t + 4) * GS_ + nc * 8 + g]);
                mma_tf32(acc_o[0][nc], pa0, gb);
                mma_tf32(acc_o[1][nc], pa1, gb);
            }
        }
    }

    l0 += __shfl_xor_sync(0xffffffffu, l0, 1);
    l0 += __shfl_xor_sync(0xffffffffu, l0, 2);
    l1 += __shfl_xor_sync(0xffffffffu, l1, 1);
    l1 += __shfl_xor_sync(0xffffffffu, l1, 2);
    l2 += __shfl_xor_sync(0xffffffffu, l2, 1);
    l2 += __shfl_xor_sync(0xffffffffu, l2, 2);
    l3 += __shfl_xor_sync(0xffffffffu, l3, 1);
    l3 += __shfl_xor_sync(0xffffffffu, l3, 2);
    float inv0 = 1.f / l0, inv1 = 1.f / l1, inv2 = 1.f / l2, inv3 = 1.f / l3;
#pragma unroll
    for (int nc = 0; nc < 4; nc++) {
        acc_o[0][nc][0] *= inv0;
        acc_o[0][nc][1] *= inv0;
        acc_o[0][nc][2] *= inv1;
        acc_o[0][nc][3] *= inv1;
        acc_o[1][nc][0] *= inv2;
        acc_o[1][nc][1] *= inv2;
        acc_o[1][nc][2] *= inv3;
        acc_o[1][nc][3] *= inv3;
    }

    __syncthreads();
    float* o_s = th_s;
#pragma unroll
    for (int tt = 0; tt < 2; tt++) {
        int r0 = qw + tt * 16 + g;
#pragma unroll
        for (int nc = 0; nc < 4; nc++) {
            *(float2*)&o_s[r0 * OS_ + nc * 8 + 2 * t] =
                make_float2(acc_o[tt][nc][0], acc_o[tt][nc][1]);
            *(float2*)&o_s[(r0 + 8) * OS_ + nc * 8 + 2 * t] =
                make_float2(acc_o[tt][nc][2], acc_o[tt][nc][3]);
        }
    }
    __syncthreads();

    {
        int q = tid;
        float ov[32];
#pragma unroll
        for (int k = 0; k < 16; k++) {
            float2 v = *(const float2*)&o_s[q * OS_ + 2 * k];
            ov[2 * k] = v.x;
            ov[2 * k + 1] = v.y;
        }
        size_t ybase = (size_t)(br * B_ + b) * C_ * N_ + q0 + q;
#pragma unroll 4
        for (int ch = 0; ch < C_; ch++) {
            const float4* wr4 = (const float4*)&Ws[ch * IC_];
            float a0 = Wbs[ch], a1 = 0.f, a2 = 0.f, a3 = 0.f;
#pragma unroll
            for (int k = 0; k < 8; k++) {
                float4 wv = wr4[k];
                a0 = fmaf(wv.x, ov[4 * k + 0], a0);
                a1 = fmaf(wv.y, ov[4 * k + 1], a1);
                a2 = fmaf(wv.z, ov[4 * k + 2], a2);
                a3 = fmaf(wv.w, ov[4 * k + 3], a3);
            }
            g_y[ybase + (size_t)ch * N_] = (a0 + a1) + (a2 + a3);
        }
    }
}

// ---------------- kernel 5b: BN sum/sumsq from g_y ------------------------
__global__ void __launch_bounds__(256) k_bn_reduce() {
    int br = blockIdx.x >> 6;
    int ch = blockIdx.x & 63;
    float s1 = 0.f, s2 = 0.f;
    for (int b = 0; b < B_; b++) {
        const float4* p = (const float4*)&g_y[((size_t)(br * B_ + b) * C_ + ch) * N_];
        for (int i = threadIdx.x; i < N_ / 4; i += 256) {
            float4 v = p[i];
            s1 += (v.x + v.y) + (v.z + v.w);
            s2 = fmaf(v.x, v.x, s2);
            s2 = fmaf(v.y, v.y, s2);
            s2 = fmaf(v.z, v.z, s2);
            s2 = fmaf(v.w, v.w, s2);
        }
    }
    __shared__ float r1[256], r2[256];
    r1[threadIdx.x] = s1;
    r2[threadIdx.x] = s2;
    __syncthreads();
    for (int s = 128; s > 0; s >>= 1) {
        if (threadIdx.x < s) {
            r1[threadIdx.x] += r1[threadIdx.x + s];
            r2[threadIdx.x] += r2[threadIdx.x + s];
        }
        __syncthreads();
    }
    if (threadIdx.x == 0) {
        g_bnsum[(br * C_ + ch) * 2 + 0] = r1[0];
        g_bnsum[(br * C_ + ch) * 2 + 1] = r2[0];
    }
}

// ---------------- kernel 6: BN stats -> per-channel scale/shift ------------
__global__ void k_bnstats(const float* __restrict__ gr, const float* __restrict__ bbr,
                          const float* __restrict__ gi, const float* __restrict__ bbi) {
    int i = threadIdx.x;
    if (i >= 2 * C_) return;
    int br = i / C_, ch = i % C_;
    float cnt = (float)(B_ * N_);
    float s = g_bnsum[i * 2], s2 = g_bnsum[i * 2 + 1];
    float mean = s / cnt;
    float var = s2 / cnt - mean * mean;
    if (var < 0.f) var = 0.f;
    float gamma = (br ? gi : gr)[ch];
    float beta = (br ? bbi : bbr)[ch];
    float sc = gamma * rsqrtf(var + 1e-5f);
    g_bnsc[i * 2 + 0] = sc;
    g_bnsc[i * 2 + 1] = beta - mean * sc;
}

// ---------------- kernel 7: BN apply + residual + write output -------------
__global__ void k_final(const float* __restrict__ rgb, const float* __restrict__ ir,
                        float* __restrict__ out) {
    size_t idx = ((size_t)blockIdx.x * 256 + threadIdx.x) * 4;
    const size_t half = (size_t)B_ * C_ * N_;
    if (idx >= 2 * half) return;
    int br = idx >= half;
    size_t rem = idx - (size_t)br * half;
    int ch = (int)((rem / N_) % C_);
    float4 y = *(const float4*)&g_y[idx];
    float4 xv = *(const float4*)&((br ? ir : rgb)[rem]);
    float sc = g_bnsc[(br * C_ + ch) * 2 + 0];
    float sh = g_bnsc[(br * C_ + ch) * 2 + 1];
    float4 r;
    r.x = fmaf(y.x, sc, sh) + xv.x;
    r.y = fmaf(y.y, sc, sh) + xv.y;
    r.z = fmaf(y.z, sc, sh) + xv.z;
    r.w = fmaf(y.w, sc, sh) + xv.w;
    *(float4*)&out[idx] = r;
}

// ---------------- launcher -------------------------------------------------
extern "C" void kernel_launch(void* const* d_in, const int* in_sizes, int n_in,
                              void* d_out, int out_size) {
    const float* rgb   = (const float*)d_in[0];
    const float* ir    = (const float*)d_in[1];
    const float* pos   = (const float*)d_in[2];
    const float* gp_w1 = (const float*)d_in[3];
    const float* gp_b1 = (const float*)d_in[4];
    const float* gp_w2 = (const float*)d_in[5];
    const float* gp_b2 = (const float*)d_in[6];
    const float* r_tw = (const float*)d_in[7];
    const float* r_tb = (const float*)d_in[8];
    const float* r_pw = (const float*)d_in[9];
    const float* r_pb = (const float*)d_in[10];
    const float* r_gw = (const float*)d_in[11];
    const float* r_gb = (const float*)d_in[12];
    const float* r_Ww = (const float*)d_in[13];
    const float* r_Wb = (const float*)d_in[14];
    const float* r_bg = (const float*)d_in[15];
    const float* r_bb = (const float*)d_in[16];
    const float* i_tw = (const float*)d_in[17];
    const float* i_tb = (const float*)d_in[18];
    const float* i_pw = (const float*)d_in[19];
    const float* i_pb = (const float*)d_in[20];
    const float* i_gw = (const float*)d_in[21];
    const float* i_gb = (const float*)d_in[22];
    const float* i_Ww = (const float*)d_in[23];
    const float* i_Wb = (const float*)d_in[24];
    const float* i_bg = (const float*)d_in[25];
    const float* i_bb = (const float*)d_in[26];
    float* out = (float*)d_out;

    static int init_done = 0;
    static cudaStream_t s2;
    static cudaEvent_t ev_fork, ev_join;
    if (!init_done) {
        cudaFuncSetAttribute(k_attn_tc, cudaFuncAttributeMaxDynamicSharedMemorySize,
                             SMEM_BYTES_);
        cudaFuncSetAttribute(k_gemm_tc, cudaFuncAttributeMaxDynamicSharedMemorySize,
                             GEMM_SMEM_BYTES);
        cudaStreamCreateWithFlags(&s2, cudaStreamNonBlocking);
        cudaEventCreateWithFlags(&ev_fork, cudaEventDisableTiming);
        cudaEventCreateWithFlags(&ev_join, cudaEventDisableTiming);
        init_done = 1;
    }

    // fork: theta+phig (side stream) run concurrently with cvt+h+gemm (main)
    cudaEventRecord(ev_fork, 0);
    cudaStreamWaitEvent(s2, ev_fork, 0);
    k_theta<<<dim3(N_ / 128, B_, 2), 128, 0, s2>>>(rgb, ir, r_tw, r_tb, i_tw, i_tb);
    k_phig<<<dim3((M_ + 127) / 128, B_, 2), 128, 0, s2>>>(
        rgb, ir, r_pw, r_pb, r_gw, r_gb, i_pw, i_pb, i_gw, i_gb);
    cudaEventRecord(ev_join, s2);

    k_w2cvt<<<(int)(((size_t)GC_ * GH_ / 4 + 255) / 256), 256>>>(gp_w2);
    k_ht<<<(GH_ * M_ + 255) / 256, 256>>>(pos, gp_w1, gp_b1);
    k_gemm_tc<<<dim3((M_ + 127) / 128, GC_ / 128), 256, GEMM_SMEM_BYTES>>>(gp_b2);

    // join: attention needs bias + theta + phi/g
    cudaStreamWaitEvent(0, ev_join, 0);
    k_attn_tc<<<dim3(N_ / QB_, B_, 2), 128, SMEM_BYTES_>>>(r_Ww, r_Wb, i_Ww, i_Wb);
    k_bn_reduce<<<2 * C_, 256>>>();
    k_bnstats<<<1, 128>>>(r_bg, r_bb, i_bg, i_bb);
    k_final<<<(int)((2ULL * B_ * C_ * N_ / 4 + 255) / 256), 256>>>(rgb, ir, out);
}